// round 16
// baseline (speedup 1.0000x reference)
#include <cuda_runtime.h>
#include <cuda_bf16.h>
#include <cuda_fp16.h>
#include <cstdint>

// ---------------------------------------------------------------------------
// GAT (3 layers, H=4 heads, concat=False/mean) for B200 (base sm_100 PTX).
//   pre0_k : round x->tf32 + transpose W0 + zero ebuf(par0) + zero cnt/flags
//   gemm_mma: persistent warp-mma tf32 GEMM + fused logits. Layer 0: blocks
//             0-3 build the CSR (count -> scan -> fill) concurrently with the
//             GEMM tiles, sequenced by co-resident spin flags.
//   aggtw_k: aggregate(layer l) + transpose W(l+1) + zero ebuf(par l+1) fused
// ---------------------------------------------------------------------------

#define N_MAX   10240
#define K_MAXD  512
#define HC_MAX  1024
#define C_MAX   256
#define H_MAX   8
#define ET_MAX  204800
#define GEMM_GRID 296
#define CSR_CTAS 4
#define EOFF (N_MAX * H_MAX)

__device__ __align__(128) __half g_h[(size_t)N_MAX * HC_MAX];
__device__ __align__(128) float g_e[4 * EOFF];   // [esrc0|edst0|esrc1|edst1]
__device__ __align__(128) float g_At[(size_t)N_MAX * K_MAXD];
__device__ __align__(128) float g_Bt[(size_t)HC_MAX * K_MAXD];
__device__ int g_rowptr[N_MAX + 1];
__device__ int g_cnt[N_MAX];
__device__ int g_cursor[N_MAX];
__device__ int g_col[ET_MAX];
__device__ int g_sync[4];

// ======================= helpers ==========================================
__device__ __forceinline__ uint32_t smem_u32(const void* p) {
    uint32_t a;
    asm("{ .reg .u64 t; cvta.to.shared.u64 t, %1; cvt.u32.u64 %0, t; }" : "=r"(a) : "l"(p));
    return a;
}

__device__ __forceinline__ float to_tf32(float v) {
    uint32_t o;
    asm("cvt.rna.tf32.f32 %0, %1;" : "=r"(o) : "f"(v));
    return __uint_as_float(o);
}

__device__ __forceinline__ void cp16(uint32_t saddr, const void* gaddr, int srcbytes) {
    asm volatile("cp.async.cg.shared.global [%0], [%1], 16, %2;"
                 :: "r"(saddr), "l"(gaddr), "r"(srcbytes) : "memory");
}
__device__ __forceinline__ void cp_commit() {
    asm volatile("cp.async.commit_group;" ::: "memory");
}
template <int NN>
__device__ __forceinline__ void cp_wait() {
    asm volatile("cp.async.wait_group %0;" :: "n"(NN) : "memory");
}

__device__ __forceinline__ void ldsm4(uint32_t* r, uint32_t addr) {
    asm volatile("ldmatrix.sync.aligned.m8n8.x4.shared.b16 {%0,%1,%2,%3}, [%4];"
                 : "=r"(r[0]), "=r"(r[1]), "=r"(r[2]), "=r"(r[3]) : "r"(addr));
}

__device__ __forceinline__ void mma_tf32(float* d, const uint32_t* a, const uint32_t* b) {
    asm volatile(
        "mma.sync.aligned.m16n8k8.row.col.f32.tf32.tf32.f32 "
        "{%0,%1,%2,%3}, {%4,%5,%6,%7}, {%8,%9}, {%0,%1,%2,%3};"
        : "+f"(d[0]), "+f"(d[1]), "+f"(d[2]), "+f"(d[3])
        : "r"(a[0]), "r"(a[1]), "r"(a[2]), "r"(a[3]), "r"(b[0]), "r"(b[1]));
}

// W [K][HC] tile transpose+round helper (one 32x32 tile per block, 256 thr)
__device__ __forceinline__ void tw_tile(const float* __restrict__ W,
                                        float* __restrict__ Bt,
                                        int K, int HC, int kb, int nb, int tid) {
    __shared__ float t[32][33];
    int tx = tid & 31, ty = tid >> 5;     // 32 x 8
    for (int i = ty; i < 32; i += 8)
        t[i][tx] = W[(size_t)(kb + i) * HC + nb + tx];
    __syncthreads();
    for (int i = ty; i < 32; i += 8)
        Bt[(size_t)(nb + i) * K + kb + tx] = to_tf32(t[tx][i]);
}

// ======================= fused layer-0 pre-kernel ==========================
__global__ void pre0_k(const float4* __restrict__ X, float4* __restrict__ At,
                       int total4, int rB,
                       const float* __restrict__ W0, float* __restrict__ Bt,
                       int K, int HC, int twB,
                       float4* __restrict__ ez, int ez4, int z1B,
                       int4* __restrict__ cz, int cz4, int* __restrict__ sy) {
    int b = blockIdx.x;
    int tid = threadIdx.x;
    if (b < twB) {
        int nxt = HC / 32;
        int kb = (b / nxt) * 32, nb = (b % nxt) * 32;
        tw_tile(W0, Bt, K, HC, kb, nb, tid);
    } else if (b < twB + rB) {
        int i0 = (b - twB) * 256 + tid;
        int stride = rB * 256;
        for (int i = i0; i < total4; i += stride) {
            float4 v = X[i];
            v.x = to_tf32(v.x); v.y = to_tf32(v.y);
            v.z = to_tf32(v.z); v.w = to_tf32(v.w);
            At[i] = v;
        }
    } else if (b < twB + rB + z1B) {
        int i0 = (b - twB - rB) * 256 + tid;
        int stride = z1B * 256;
        float4 z = make_float4(0.f, 0.f, 0.f, 0.f);
        for (int i = i0; i < ez4; i += stride) ez[i] = z;
    } else {
        int bb = b - twB - rB - z1B;
        int i0 = bb * 256 + tid;
        int stride = 4 * 256;
        int4 z = make_int4(0, 0, 0, 0);
        for (int i = i0; i < cz4; i += stride) cz[i] = z;
        if (bb == 0 && tid < 4) sy[tid] = 0;
    }
}

// ======================= persistent warp-mma tf32 GEMM + fused logits ======
// Layer 0: blocks 0..3 build the CSR (count -> single-block scan -> fill),
// sequenced by co-resident spin flags; blocks >= 4 run the GEMM tiles.
#define GEMM_SMEM 65536

__global__ __launch_bounds__(256, 2)
void gemm_mma(const float* __restrict__ At, const float* __restrict__ Bt,
              __half* __restrict__ C, const float* __restrict__ as_g,
              const float* __restrict__ ad_g, float* __restrict__ esrc,
              float* __restrict__ edst, int M, int Ncols, int K, int Cc, int H,
              int ntiles_x, int ntiles,
              const int* __restrict__ srcE, const int* __restrict__ dstE,
              int E, int Nn, int docsr,
              int* __restrict__ cnt, int* __restrict__ rowptr,
              int* __restrict__ cursor, int* __restrict__ colA,
              int* __restrict__ sy) {
    extern __shared__ __align__(1024) char smem[];
    const int tid = threadIdx.x;
    const int bid = blockIdx.x;

    // ---------------- CSR branch (layer 0, blocks 0..3) ----------------
    if (docsr && bid < CSR_CTAS) {
        const int tot = E + Nn;
        const int chunk = (tot + CSR_CTAS - 1) / CSR_CTAS;
        const int i0 = bid * chunk;
        int i1 = i0 + chunk; if (i1 > tot) i1 = tot;
        // count
        for (int i = i0 + tid; i < i1; i += 256) {
            int d = (i < E) ? dstE[i] : (i - E);
            atomicAdd(&cnt[d], 1);
        }
        __threadfence();
        __syncthreads();
        if (tid == 0) atomicAdd(&sy[0], 1);

        if (bid == 0) {
            if (tid == 0) { while (atomicAdd(&sy[0], 0) < CSR_CTAS) {} }
            __syncthreads();
            // exclusive scan over cnt -> rowptr + cursor (256 threads)
            __shared__ int wsum[8];
            __shared__ int carry_sh;
            int lane = tid & 31, wid = tid >> 5;
            if (tid == 0) carry_sh = 0;
            __syncthreads();
            for (int base = 0; base < Nn; base += 256) {
                int v = (base + tid < Nn) ? cnt[base + tid] : 0;
                int x = v;
#pragma unroll
                for (int o = 1; o < 32; o <<= 1) {
                    int t = __shfl_up_sync(0xffffffffu, x, o);
                    if (lane >= o) x += t;
                }
                if (lane == 31) wsum[wid] = x;
                __syncthreads();
                if (wid == 0 && lane < 8) {
                    int s = wsum[lane];
#pragma unroll
                    for (int o = 1; o < 8; o <<= 1) {
                        int t = __shfl_up_sync(0xffu, s, o);
                        if (lane >= o) s += t;
                    }
                    wsum[lane] = s;
                }
                __syncthreads();
                int cin = carry_sh;
                int incl = x + ((wid > 0) ? wsum[wid - 1] : 0);
                if (base + tid < Nn) {
                    int rp = cin + incl - v;
                    rowptr[base + tid] = rp;
                    cursor[base + tid] = rp;
                }
                __syncthreads();
                if (tid == 0) carry_sh = cin + wsum[7];
                __syncthreads();
            }
            if (tid == 0) rowptr[Nn] = carry_sh;
            __threadfence();
            __syncthreads();
            if (tid == 0) atomicExch(&sy[1], 1);
        }

        if (tid == 0) { while (atomicAdd(&sy[1], 0) == 0) {} }
        __syncthreads();
        // fill
        for (int i = i0 + tid; i < i1; i += 256) {
            int s, d;
            if (i < E) { s = srcE[i]; d = dstE[i]; }
            else       { s = d = i - E; }
            int pos = atomicAdd(&cursor[d], 1);
            colA[pos] = s;
        }
        return;
    }

    // ---------------- GEMM branch ----------------
    const uint32_t sbase = smem_u32(smem);
    const int lane = tid & 31, wid = tid >> 5;
    const int warp_m = wid & 3;
    const int warp_n = wid >> 2;
    const int g = lane >> 3, r = lane & 7;
    const int nch = K >> 5;
    const int tstart = docsr ? (bid - CSR_CTAS) : bid;
    const int tstride = docsr ? (gridDim.x - CSR_CTAS) : gridDim.x;

    for (int tile = tstart; tile < ntiles; tile += tstride) {
        const int mtile = tile / ntiles_x;
        const int ntile = tile - mtile * ntiles_x;

        float acc[2][8][4] = {};

        auto load_stage = [&](int buf, int ch) {
            const int kb = ch << 5;
            const uint32_t sb = sbase + buf * 32768;
#pragma unroll
            for (int j = 0; j < 4; ++j) {
                int chunk = tid + (j << 8);
                int m = chunk >> 3, c = chunk & 7;
                uint32_t soff = m * 128 + ((c ^ (m & 7)) << 4);
                int arow = mtile * 128 + m;
                int aval = (arow < M) ? 16 : 0;
                int ar = (arow < M) ? arow : (M - 1);
                cp16(sb + soff, At + (size_t)ar * K + kb + c * 4, aval);
                int brow = ntile * 128 + m;
                cp16(sb + 16384 + soff, Bt + (size_t)brow * K + kb + c * 4, 16);
            }
        };

        load_stage(0, 0);
        cp_commit();

        for (int ch = 0; ch < nch; ++ch) {
            const int nxt = ch + 1;
            if (nxt < nch) { load_stage(nxt & 1, nxt); cp_commit(); }
            if (nxt < nch) cp_wait<1>(); else cp_wait<0>();
            __syncthreads();

            const uint32_t sb = sbase + (ch & 1) * 32768;
#pragma unroll
            for (int k8 = 0; k8 < 4; ++k8) {
                const int c0 = k8 * 2;
                uint32_t af[2][4], bf[8][2];
#pragma unroll
                for (int mt = 0; mt < 2; ++mt) {
                    int ml = warp_m * 32 + mt * 16 + r + ((g & 1) << 3);
                    int cc = c0 + (g >> 1);
                    uint32_t ad = sb + ml * 128 + ((cc ^ (ml & 7)) << 4);
                    ldsm4(af[mt], ad);
                }
#pragma unroll
                for (int nt2 = 0; nt2 < 4; ++nt2) {
                    int nl = warp_n * 64 + nt2 * 16 + r + ((g >> 1) << 3);
                    int cc = c0 + (g & 1);
                    uint32_t bd = sb + 16384 + nl * 128 + ((cc ^ (nl & 7)) << 4);
                    uint32_t tb[4];
                    ldsm4(tb, bd);
                    bf[nt2 * 2][0] = tb[0]; bf[nt2 * 2][1] = tb[1];
                    bf[nt2 * 2 + 1][0] = tb[2]; bf[nt2 * 2 + 1][1] = tb[3];
                }
#pragma unroll
                for (int mt = 0; mt < 2; ++mt)
#pragma unroll
                    for (int nt = 0; nt < 8; ++nt)
                        mma_tf32(acc[mt][nt], af[mt], bf[nt]);
            }
            __syncthreads();
        }

        // epilogue 1: store C as fp16
#pragma unroll
        for (int mt = 0; mt < 2; ++mt) {
            int row0 = mtile * 128 + warp_m * 32 + mt * 16 + (lane >> 2);
#pragma unroll
            for (int nt = 0; nt < 8; ++nt) {
                int col = ntile * 128 + warp_n * 64 + nt * 8 + (lane & 3) * 2;
                if (row0 < M)
                    *reinterpret_cast<__half2*>(&C[(size_t)row0 * Ncols + col]) =
                        __floats2half2_rn(acc[mt][nt][0], acc[mt][nt][1]);
                if (row0 + 8 < M)
                    *reinterpret_cast<__half2*>(&C[(size_t)(row0 + 8) * Ncols + col]) =
                        __floats2half2_rn(acc[mt][nt][2], acc[mt][nt][3]);
            }
        }

        // epilogue 2: fused logits partial dots
        float es[4] = {0.f, 0.f, 0.f, 0.f}, ed[4] = {0.f, 0.f, 0.f, 0.f};
#pragma unroll
        for (int nt = 0; nt < 8; ++nt) {
            int col = ntile * 128 + warp_n * 64 + nt * 8 + (lane & 3) * 2;
            float a0 = as_g[col], a1 = as_g[col + 1];
            float d0 = ad_g[col], d1 = ad_g[col + 1];
#pragma unroll
            for (int mt = 0; mt < 2; ++mt) {
                es[mt * 2 + 0] += acc[mt][nt][0] * a0 + acc[mt][nt][1] * a1;
                es[mt * 2 + 1] += acc[mt][nt][2] * a0 + acc[mt][nt][3] * a1;
                ed[mt * 2 + 0] += acc[mt][nt][0] * d0 + acc[mt][nt][1] * d1;
                ed[mt * 2 + 1] += acc[mt][nt][2] * d0 + acc[mt][nt][3] * d1;
            }
        }
#pragma unroll
        for (int o = 1; o <= 2; o <<= 1)
#pragma unroll
            for (int i = 0; i < 4; ++i) {
                es[i] += __shfl_xor_sync(0xffffffffu, es[i], o);
                ed[i] += __shfl_xor_sync(0xffffffffu, ed[i], o);
            }
        if ((lane & 3) == 0) {
            int hh = (ntile * 128 + warp_n * 64) / Cc;
#pragma unroll
            for (int mt = 0; mt < 2; ++mt) {
                int row = mtile * 128 + warp_m * 32 + mt * 16 + (lane >> 2);
                if (row < M) {
                    atomicAdd(&esrc[row * H + hh], es[mt * 2 + 0]);
                    atomicAdd(&edst[row * H + hh], ed[mt * 2 + 0]);
                }
                if (row + 8 < M) {
                    atomicAdd(&esrc[(row + 8) * H + hh], es[mt * 2 + 1]);
                    atomicAdd(&edst[(row + 8) * H + hh], ed[mt * 2 + 1]);
                }
            }
        }
        __syncthreads();
    }
}

// ======================= fused aggregate + next-layer prep =================
#define AGG_CAP 128

__global__ __launch_bounds__(256)
void aggtw_k(const __half* __restrict__ hbuf,
             const float* __restrict__ esrc, const float* __restrict__ edst,
             const int* __restrict__ rowptr, const int* __restrict__ col,
             const float* __restrict__ bias, float* __restrict__ out,
             float* __restrict__ anext, int write_out,
             int H, int C, int HC, float invH, int N, int aggB,
             const float* __restrict__ Wn, float* __restrict__ Bt,
             int Kn, int HCn, int twB,
             float4* __restrict__ ez, int ez4, int zB) {
    const int b = blockIdx.x;
    const int tid = threadIdx.x;

    if (b >= aggB) {
        if (b < aggB + twB) {
            int bb = b - aggB;
            int nxt = HCn / 32;
            int kb = (bb / nxt) * 32, nb = (bb % nxt) * 32;
            tw_tile(Wn, Bt, Kn, HCn, kb, nb, tid);
        } else if (zB > 0) {
            int i0 = (b - aggB - twB) * 256 + tid;
            int stride = zB * 256;
            float4 z = make_float4(0.f, 0.f, 0.f, 0.f);
            for (int i = i0; i < ez4; i += stride) ez[i] = z;
        }
        return;
    }

    __shared__ float sh_dinv[2][H_MAX];
    __shared__ float w_sh[2][AGG_CAP * 4];
    __shared__ int col_sh[2][AGG_CAP];
    __shared__ float red_sh[2][HC_MAX];
    __shared__ int s_iters;

    const int half = tid >> 7;
    const int u = tid & 127;
    const int hh = u >> 5;
    const int q = u & 31;
    const int n = b * 2 + half;
    const bool nok = (n < N);

    int start = 0, end = 0;
    if (nok) { start = rowptr[n]; end = rowptr[n + 1]; }
    const int len = end - start;

    if (tid == 0) s_iters = 0;
    __syncthreads();
    if (u == 0 && nok) atomicMax(&s_iters, (len + AGG_CAP - 1) / AGG_CAP);
    __syncthreads();
    const int iters = s_iters;

    const float edh = nok ? edst[n * H + hh] : 0.f;
    float ssum = 0.f;

    const int base = hh * C + (q << 3);
    float a0 = 0.f, a1 = 0.f, a2 = 0.f, a3 = 0.f,
          a4 = 0.f, a5 = 0.f, a6 = 0.f, a7 = 0.f;

    for (int it = 0; it < iters; ++it) {
        int cb = start + it * AGG_CAP;
        int cnt = end - cb;
        if (cnt > AGG_CAP) cnt = AGG_CAP;
        if (cnt > 0) {
            for (int e = q; e < cnt; e += 32) {
                int s = col[cb + e];
                if (hh == 0) col_sh[half][e] = s;
                float v = esrc[s * H + hh] + edh;
                v = v > 0.f ? v : 0.2f * v;
                float w = __expf(fminf(v, 60.f));
                w_sh[half][e * 4 + hh] = w;
                ssum += w;
            }
        }
        __syncthreads();
        if (cnt > 0) {
            for (int e = 0; e < cnt; ++e) {
                const uint4 pv = *reinterpret_cast<const uint4*>(
                    hbuf + (size_t)col_sh[half][e] * HC + base);
                const float w = w_sh[half][e * 4 + hh];
                const float2 v01 = __half22float2(*reinterpret_cast<const __half2*>(&pv.x));
                const float2 v23 = __half22float2(*reinterpret_cast<const __half2*>(&pv.y));
                const float2 v45 = __half22float2(*reinterpret_cast<const __half2*>(&pv.z));
                const float2 v67 = __half22float2(*reinterpret_cast<const __half2*>(&pv.w));
                a0 += w * v01.x; a1 += w * v01.y;
                a2 += w * v23.x; a3 += w * v23.y;
                a4 += w * v45.x; a5 += w * v45.y;
                a6 += w * v67.x; a7 += w * v67.y;
            }
        }
        __syncthreads();
    }

#pragma unroll
    for (int o = 16; o > 0; o >>= 1) ssum += __shfl_xor_sync(0xffffffffu, ssum, o);
    if (q == 0) sh_dinv[half][hh] = 1.f / (ssum + 1e-16f);
    __syncthreads();

    {
        const float dinv = sh_dinv[half][hh];
        float* rp = &red_sh[half][base];
        rp[0] = a0 * dinv; rp[1] = a1 * dinv; rp[2] = a2 * dinv; rp[3] = a3 * dinv;
        rp[4] = a4 * dinv; rp[5] = a5 * dinv; rp[6] = a6 * dinv; rp[7] = a7 * dinv;
    }
    __syncthreads();

    if (nok) {
        const int cpt = C >> 7;
        for (int j = 0; j < cpt; ++j) {
            int c = u + j * 128;
            float s = 0.f;
#pragma unroll 4
            for (int h = 0; h < H; ++h) s += red_sh[half][h * C + c];
            float val = s * invH + bias[c];
            if (write_out) out[(size_t)n * C + c] = val;
            else           anext[(size_t)n * C + c] = to_tf32(val);
        }
    }
}

// ======================= host launcher =====================================
extern "C" void kernel_launch(void* const* d_in, const int* in_sizes, int n_in,
                              void* d_out, int out_size) {
    const float* x  = (const float*)d_in[0];
    const int*   ei = (const int*)d_in[1];
    const float* W[3]  = {(const float*)d_in[2],  (const float*)d_in[6],  (const float*)d_in[10]};
    const float* AS[3] = {(const float*)d_in[3],  (const float*)d_in[7],  (const float*)d_in[11]};
    const float* AD[3] = {(const float*)d_in[4],  (const float*)d_in[8],  (const float*)d_in[12]};
    const float* B[3]  = {(const float*)d_in[5],  (const float*)d_in[9],  (const float*)d_in[13]};

    const int Cc[3] = {in_sizes[5], in_sizes[9], in_sizes[13]};
    const int H = in_sizes[3] / Cc[0];
    const int E = in_sizes[1] / 2;
    const int N = out_size / Cc[2];
    const int F_IN = in_sizes[0] / N;

    __half* hbuf;
    float *ebuf, *At, *Bt;
    int *rowptr, *cnt, *cursor, *col, *sy;
    cudaGetSymbolAddress((void**)&hbuf,   g_h);
    cudaGetSymbolAddress((void**)&ebuf,   g_e);
    cudaGetSymbolAddress((void**)&At,     g_At);
    cudaGetSymbolAddress((void**)&Bt,     g_Bt);
    cudaGetSymbolAddress((void**)&rowptr, g_rowptr);
    cudaGetSymbolAddress((void**)&cnt,    g_cnt);
    cudaGetSymbolAddress((void**)&cursor, g_cursor);
    cudaGetSymbolAddress((void**)&col,    g_col);
    cudaGetSymbolAddress((void**)&sy,     g_sync);

    cudaFuncSetAttribute(gemm_mma, cudaFuncAttributeMaxDynamicSharedMemorySize, GEMM_SMEM);

    const int aggB = (N + 1) / 2;
    const int ez4 = (2 * EOFF) / 4;

    // ---- fused layer-0 pre-work (zeroes cnt + sync flags too) ----
    {
        int HC0 = H * Cc[0];
        int twB = (HC0 / 32) * (F_IN / 32);
        int total4 = (N * F_IN) >> 2;
        int rB = 1280, z1B = 32, z2B = 4;
        pre0_k<<<twB + rB + z1B + z2B, 256>>>(
            (const float4*)x, (float4*)At, total4, rB,
            W[0], Bt, F_IN, HC0, twB,
            (float4*)ebuf, ez4, z1B,
            (int4*)cnt, (N + 3) / 4, sy);
    }

    int K = F_IN;
    for (int l = 0; l < 3; ++l) {
        int C = Cc[l], HC = H * C;
        int par = l & 1;
        float* esrc = ebuf + par * 2 * EOFF;
        float* edst = esrc + EOFF;

        {
            int nx = HC / 128;
            int ntiles = nx * ((N + 127) / 128);
            int docsr = (l == 0) ? 1 : 0;
            int grid = GEMM_GRID;
            int need = ntiles + (docsr ? CSR_CTAS : 0);
            if (grid > need) grid = need;
            gemm_mma<<<grid, 256, GEMM_SMEM>>>(At, Bt, hbuf,
                                               AS[l], AD[l], esrc, edst,
                                               N, HC, K, C, H, nx, ntiles,
                                               ei, ei + E, E, N, docsr,
                                               cnt, rowptr, cursor, col, sy);
        }

        if (l < 2) {
            int Kn = C, HCn = H * Cc[l + 1];
            int twB = (HCn / 32) * (Kn / 32);
            int zB = 32;
            float4* ezn = (float4*)(ebuf + ((l + 1) & 1) * 2 * EOFF);
            aggtw_k<<<aggB + twB + zB, 256>>>(
                hbuf, esrc, edst, rowptr, col, B[l], (float*)d_out, At, 0,
                H, C, HC, 1.0f / (float)H, N, aggB,
                W[l + 1], Bt, Kn, HCn, twB, ezn, ez4, zB);
        } else {
            aggtw_k<<<aggB, 256>>>(
                hbuf, esrc, edst, rowptr, col, B[l], (float*)d_out, At, 1,
                H, C, HC, 1.0f / (float)H, N, aggB,
                nullptr, nullptr, 0, 0, 0, nullptr, 0, 0);
        }
        K = C;
    }
}